// round 9
// baseline (speedup 1.0000x reference)
#include <cuda_runtime.h>
#include <cstdint>

#define BB 1024
#define VV 8
#define NDm 32
#define NPm 16
#define NMm 24
#define DD 256
#define VOC_D 2000
#define VOC_P 1500
#define VOC_M 131

// ---------------- scratch layout (floats) ----------------
#define OFF_HED   0L
#define OFF_HEP   512000L
#define OFF_HEM   896000L
#define OFF_TEMD  929536L
#define OFF_TEMP  963072L
#define OFF_TEDM  996608L
#define OFF_TEPM  1508608L
#define OFF_SEQ   1892608L        // [3][8192][256]
#define OFF_GI    8184064L        // [3][8192][768]
#define OFF_H0    27058432L       // [3][1024][256]
#define OFF_H1    27844864L       // [3][1024][256]
#define OFF_HR    28631296L       // [1024][768]
#define OFF_WQ2   29417728L       // [256][768]
#define OFF_BQP   29614336L       // [256]
#define OFF_SP    29614592L       // [1024][256]
#define OFF_PART  29876736L       // [1024]
#define OFF_WIHP  29877760L       // [3][768][256] permuted
#define OFF_WHHP  30467584L       // [3][768][256] permuted
#define OFF_BIHP  31057408L       // [3][768]
#define OFF_BHHP  31059712L       // [3][768]
#define SCRATCH_TOTAL 31062016L

__device__ __align__(256) float g_scratch[SCRATCH_TOTAL];

__device__ __forceinline__ float sigm(float x) { return 1.0f / (1.0f + expf(-x)); }
__device__ __forceinline__ uint32_t f2tf32(float x) {
    uint32_t r;
    asm("cvt.rna.tf32.f32 %0, %1;" : "=r"(r) : "f"(x));
    return r;
}
__device__ __forceinline__ void cpa16(float* smem, const float* g) {
    uint32_t s = (uint32_t)__cvta_generic_to_shared(smem);
    asm volatile("cp.async.ca.shared.global [%0], [%1], 16;" :: "r"(s), "l"(g));
}
__device__ __forceinline__ void cpa_commit() {
    asm volatile("cp.async.commit_group;");
}

// ---------------- Fused precompute: 7 table jobs + Wq2 + GRU weight permutes ----
__global__ __launch_bounds__(256) void tables_kernel(
    const float* __restrict__ E_diag, const float* __restrict__ E_proc,
    const float* __restrict__ E_med,  const float* __restrict__ W_homo,
    const float* __restrict__ Wh_d,   const float* __restrict__ Wh_p,
    const float* __restrict__ Wh_md,  const float* __restrict__ Wh_mp,
    const float* __restrict__ Wq,     const float* __restrict__ bq,
    const float* __restrict__ gru_wih, const float* __restrict__ gru_whh,
    const float* __restrict__ gru_bih, const float* __restrict__ gru_bhh,
    float* __restrict__ HEd, float* __restrict__ HEp, float* __restrict__ HEm,
    float* __restrict__ Temd, float* __restrict__ Temp_,
    float* __restrict__ Tedm, float* __restrict__ Tepm,
    float* __restrict__ Wq2p, float* __restrict__ bqp,
    float* __restrict__ WIHP, float* __restrict__ WHHP,
    float* __restrict__ BIHP, float* __restrict__ BHHP)
{
    int blk = blockIdx.x;
    int tid = threadIdx.x;

    if (blk >= 1009) {                        // ---- bias permutes ----
        for (int e = tid; e < 2304; e += 256) {
            int z = e / 768, np = e % 768, d = np / 3, g = np % 3;
            BIHP[e] = gru_bih[(long)z * 768 + g * 256 + d];
            BHHP[e] = gru_bhh[(long)z * 768 + g * 256 + d];
        }
        return;
    }
    if (blk >= 721) {                         // ---- weight permutes ----
        int k = blk - 721;
        for (int i = 0; i < 16; i++) {
            int gr = k * 16 + i;
            int t = gr / 2304;
            int rr = gr % 2304;
            int z = rr / 768, np = rr % 768, d = np / 3, g = np % 3;
            const float* src;
            float* dst;
            if (t == 0) {
                src = gru_wih + ((long)z * 768 + g * 256 + d) * 256;
                dst = WIHP + ((long)z * 768 + np) * 256;
            } else {
                src = gru_whh + ((long)z * 768 + g * 256 + d) * 256;
                dst = WHHP + ((long)z * 768 + np) * 256;
            }
            dst[tid] = src[tid];
        }
        return;
    }
    if (blk >= 465) {                         // ---- Wq2 fold ----
        int j = blk - 465;
        for (int c = tid; c < 768; c += 256) {
            float v = 0.0f;
            if (j < VOC_M) v = Wq[(long)j * 1536 + c] + Wq[(long)j * 1536 + 768 + c];
            Wq2p[(long)j * 768 + c] = v;
        }
        if (tid == 0) bqp[j] = (j < VOC_M) ? bq[j] : 0.0f;
        return;
    }

    const float* E; const float* W; float* dst; int rows; int r0;
    if (blk < 125)      { E = E_diag; W = W_homo;          dst = HEd;   rows = VOC_D; r0 = blk * 16; }
    else if (blk < 219) { E = E_proc; W = W_homo + 65536;  dst = HEp;   rows = VOC_P; r0 = (blk-125)*16; }
    else if (blk < 228) { E = E_med;  W = W_homo + 131072; dst = HEm;   rows = VOC_M; r0 = (blk-219)*16; }
    else if (blk < 237) { E = E_med;  W = Wh_d;            dst = Temd;  rows = VOC_M; r0 = (blk-228)*16; }
    else if (blk < 246) { E = E_med;  W = Wh_p;            dst = Temp_; rows = VOC_M; r0 = (blk-237)*16; }
    else if (blk < 371) { E = E_diag; W = Wh_md;           dst = Tedm;  rows = VOC_D; r0 = (blk-246)*16; }
    else                { E = E_proc; W = Wh_mp;           dst = Tepm;  rows = VOC_P; r0 = (blk-371)*16; }

    __shared__ __align__(16) float e[16][DD];
    for (int i = tid; i < 16 * (DD / 4); i += 256) {
        int rr = i >> 6;
        int cc = (i & 63) << 2;
        float4 v = make_float4(0.f, 0.f, 0.f, 0.f);
        if (r0 + rr < rows) v = *(const float4*)&E[(long)(r0 + rr) * DD + cc];
        *(float4*)&e[rr][cc] = v;
    }
    __syncthreads();

    float acc[16];
#pragma unroll
    for (int i = 0; i < 16; i++) acc[i] = 0.0f;
#pragma unroll 4
    for (int k = 0; k < DD; k++) {
        float w = W[(long)k * DD + tid];
#pragma unroll
        for (int i = 0; i < 16; i++) acc[i] += e[i][k] * w;
    }
#pragma unroll
    for (int i = 0; i < 16; i++)
        if (r0 + i < rows) dst[(long)(r0 + i) * DD + tid] = acc[i];
}

// ---------------- fused graph kernel: all 3 phases concurrent ------------------
// dynamic smem (floats):
//  hbuf 72*260=18720 | Sbuf 72*33=2376 | abuf 1856 | pbuf 8*3*33=792 |
//  csm 3*32=96 | wdm 768 | wpm 384 | sidx 72(int) | srho 8  => 25072 fl = 100288 B
#define GHP 260
#define GRAPH_SMEM 100288

__global__ __launch_bounds__(256) void graph_kernel(
    const int* __restrict__ idx_diag, const int* __restrict__ idx_proc,
    const int* __restrict__ idx_med,
    const float* __restrict__ adj_diag, const float* __restrict__ adj_proc,
    const float* __restrict__ adj_med,
    const float* __restrict__ w_dm, const float* __restrict__ w_pm,
    const float* __restrict__ rho,
    const float* __restrict__ HEd, const float* __restrict__ HEp,
    const float* __restrict__ HEm,
    const float* __restrict__ Temd, const float* __restrict__ Temp_,
    const float* __restrict__ Tedm, const float* __restrict__ Tepm,
    float* __restrict__ seq)
{
    extern __shared__ __align__(16) float gsm[];
    float* hbuf = gsm;                 // 18720
    float* Sbuf = gsm + 18720;         // 2376
    float* abuf = gsm + 21096;         // 1856
    float* pbuf = gsm + 22952;         // 792  [(w*3+ph)*33 + col]
    float* csm  = gsm + 23744;         // 96   [ph*32 + col]
    float* wdm  = gsm + 23840;         // 768
    float* wpm  = gsm + 24608;         // 384
    int*   sidx = (int*)(gsm + 24992); // 72
    float* srho = gsm + 25064;         // 8
    // hetero scratch (reuses pbuf after csm barrier)
    float* rsd = pbuf;        float* csd = pbuf + 32;
    float* rsp = pbuf + 56;   float* csp = pbuf + 72;
    float* gd  = pbuf + 96;   float* fd  = pbuf + 120;
    float* gp  = pbuf + 152;  float* fp  = pbuf + 176;

    int tid = threadIdx.x;
    int row = blockIdx.x;
    int v = row % VV;

    if (tid < 32)                  sidx[tid] = idx_diag[(long)row * NDm + tid];
    else if (tid < 48)             sidx[tid] = idx_proc[(long)row * NPm + (tid - 32)];
    else if (tid < 72)             sidx[tid] = (v > 0) ? idx_med[(long)(row - 1) * NMm + (tid - 48)] : 0;
    if (tid >= 128 && tid < 134)   srho[tid - 128] = rho[tid - 128];
    __syncthreads();

    // -------- bulk cp.async prefetch: h rows + adjacency + w_dm/w_pm --------
    for (int i = tid; i < 72 * 64; i += 256) {
        int r = i >> 6, c4 = (i & 63) << 2;
        const float* src;
        if (r < 32)      src = HEd + (long)sidx[r] * DD + c4;
        else if (r < 48) src = HEp + (long)sidx[r] * DD + c4;
        else             src = HEm + (long)sidx[r] * DD + c4;
        cpa16(&hbuf[r * GHP + c4], src);
    }
    for (int i = tid; i < 464; i += 256) {
        int fo = i << 2;
        if (fo < 1024)      cpa16(&abuf[fo], adj_diag + (long)row * 1024 + fo);
        else if (fo < 1280) cpa16(&abuf[fo], adj_proc + (long)row * 256 + (fo - 1024));
        else                cpa16(&abuf[fo], adj_med  + (long)row * 576 + (fo - 1280));
    }
    if (v > 0) {
        for (int i = tid; i < 288; i += 256) {
            int fo = i << 2;
            if (fo < 768) cpa16(&wdm[fo], w_dm + (long)row * 768 + fo);
            else          cpa16(&wpm[fo - 768], w_pm + (long)row * 384 + (fo - 768));
        }
    }
    cpa_commit();
    asm volatile("cp.async.wait_group 0;");
    __syncthreads();

    int warp = tid >> 5, l = tid & 31;
    int lq = l >> 2, lk = l & 3;

    // -------- all Gram tiles (8 d + 2 p + 6 m) over 8 warps --------
    const int t_ph[16] = {0,0,0,0,0,0,0,0, 1,1, 2,2,2,2,2,2};
    const int t_wm[16] = {0,0,0,0,1,1,1,1, 0,0, 0,0,0,1,1,1};
    const int t_wn[16] = {0,1,2,3,0,1,2,3, 0,1, 0,1,2,0,1,2};
#pragma unroll
    for (int tt = warp; tt < 16; tt += 8) {
        int ph = t_ph[tt], wm = t_wm[tt], wn = t_wn[tt];
        int pb = (ph == 0) ? 0 : (ph == 1) ? 32 : 48;
        int N  = (ph == 0) ? 32 : (ph == 1) ? 16 : 24;
        const float* Ab = &hbuf[(pb + wm * 16 + lq) * GHP + lk];
        const float* Bb = &hbuf[(pb + wn * 8 + lq) * GHP + lk];
        float c0 = 0.f, c1 = 0.f, c2 = 0.f, c3 = 0.f;
#pragma unroll 4
        for (int k = 0; k < DD; k += 8) {
            uint32_t a0 = f2tf32(Ab[k]);
            uint32_t a1 = f2tf32(Ab[8 * GHP + k]);
            uint32_t a2 = f2tf32(Ab[k + 4]);
            uint32_t a3 = f2tf32(Ab[8 * GHP + k + 4]);
            uint32_t b0 = f2tf32(Bb[k]);
            uint32_t b1 = f2tf32(Bb[k + 4]);
            asm volatile(
                "mma.sync.aligned.m16n8k8.row.col.f32.tf32.tf32.f32 "
                "{%0,%1,%2,%3}, {%4,%5,%6,%7}, {%8,%9}, {%0,%1,%2,%3};"
                : "+f"(c0), "+f"(c1), "+f"(c2), "+f"(c3)
                : "r"(a0), "r"(a1), "r"(a2), "r"(a3), "r"(b0), "r"(b1));
        }
        int rl = wm * 16 + lq;
        int r0 = pb + rl, cc = wn * 8 + 2 * lk;
        if (rl < N) {
            Sbuf[r0 * 33 + cc]     = c0 * 0.0625f;
            Sbuf[r0 * 33 + cc + 1] = c1 * 0.0625f;
        }
        if (rl + 8 < N) {
            Sbuf[(r0 + 8) * 33 + cc]     = c2 * 0.0625f;
            Sbuf[(r0 + 8) * 33 + cc + 1] = c3 * 0.0625f;
        }
    }
    __syncthreads();

    // -------- softmax over all 72 rows (9 per warp), fused colsums --------
    float acc0 = 0.f, acc1 = 0.f, acc2 = 0.f;
#pragma unroll
    for (int i = 0; i < 9; i++) {
        int r = warp * 9 + i;
        int ph = (r < 32) ? 0 : (r < 48) ? 1 : 2;
        if (ph == 2 && v == 0) continue;
        int pb = (ph == 0) ? 0 : (ph == 1) ? 32 : 48;
        int N  = (ph == 0) ? 32 : (ph == 1) ? 16 : 24;
        int ab = (ph == 0) ? 0 : (ph == 1) ? 1024 : 1280;
        int n = r - pb;
        bool ok = (l < N) && ((abuf[ab + n * N + l] > 0.5f) || (l == n));
        float s = ok ? Sbuf[r * 33 + l] : -1e30f;
        float mx = s;
#pragma unroll
        for (int o = 16; o; o >>= 1) mx = fmaxf(mx, __shfl_xor_sync(0xffffffffu, mx, o));
        float e = ok ? expf(s - mx) : 0.0f;
        float sum = e;
#pragma unroll
        for (int o = 16; o; o >>= 1) sum += __shfl_xor_sync(0xffffffffu, sum, o);
        float c = e / sum;
        if (ph == 0) acc0 += c; else if (ph == 1) acc1 += c; else acc2 += c;
    }
    pbuf[(warp * 3 + 0) * 33 + l] = acc0;
    pbuf[(warp * 3 + 1) * 33 + l] = acc1;
    pbuf[(warp * 3 + 2) * 33 + l] = acc2;
    __syncthreads();

    if (tid < 96) {
        int ph = tid >> 5, c = tid & 31;
        float s = 0.f;
#pragma unroll
        for (int w = 0; w < 8; w++) s += pbuf[(w * 3 + ph) * 33 + c];
        csm[ph * 32 + c] = s;
    }
    __syncthreads();

    // -------- out reductions (all threads; d = tid) --------
    float od_ = 0.f, op_ = 0.f, om_ = 0.f;
#pragma unroll 4
    for (int m = 0; m < 32; m++) od_ += csm[m] * hbuf[m * GHP + tid];
#pragma unroll 4
    for (int m = 0; m < 16; m++) op_ += csm[32 + m] * hbuf[(32 + m) * GHP + tid];
#pragma unroll 4
    for (int m = 0; m < 24; m++) om_ += csm[64 + m] * hbuf[(48 + m) * GHP + tid];

    float hd2 = 0.f, hp2 = 0.f, hm2 = 0.f;
    if (v > 0) {
        __syncthreads();   // pbuf reuse: all csm reads done
        if (tid < NDm) {
            float s = 0; for (int m = 0; m < NMm; m++) s += wdm[tid * NMm + m];
            rsd[tid] = s;
        }
        if (tid >= 32 && tid < 32 + NMm) {
            int m = tid - 32; float s = 0;
            for (int n = 0; n < NDm; n++) s += wdm[n * NMm + m];
            csd[m] = s;
        }
        if (tid >= 64 && tid < 64 + NPm) {
            int n = tid - 64; float s = 0;
            for (int m = 0; m < NMm; m++) s += wpm[n * NMm + m];
            rsp[n] = s;
        }
        if (tid >= 96 && tid < 96 + NMm) {
            int m = tid - 96; float s = 0;
            for (int n = 0; n < NPm; n++) s += wpm[n * NMm + m];
            csp[m] = s;
        }
        __syncthreads();
        if (tid < NMm) {
            float s = 0;
            for (int n = 0; n < NDm; n++) s += wdm[n * NMm + tid] / (rsd[n] + 1e-8f);
            gd[tid] = s;
        }
        if (tid >= 32 && tid < 32 + NDm) {
            int n = tid - 32; float s = 0;
            for (int m = 0; m < NMm; m++) s += wdm[n * NMm + m] / (csd[m] + 1e-8f);
            fd[n] = s;
        }
        if (tid >= 64 && tid < 64 + NMm) {
            int m = tid - 64; float s = 0;
            for (int n = 0; n < NPm; n++) s += wpm[n * NMm + m] / (rsp[n] + 1e-8f);
            gp[m] = s;
        }
        if (tid >= 96 && tid < 96 + NPm) {
            int n = tid - 96; float s = 0;
            for (int m = 0; m < NMm; m++) s += wpm[n * NMm + m] / (csp[m] + 1e-8f);
            fp[n] = s;
        }
        __syncthreads();

        for (int m = 0; m < NMm; m++) {
            long base = (long)sidx[48 + m] * DD + tid;
            hd2 += gd[m] * Temd[base];
            hp2 += gp[m] * Temp_[base];
        }
        for (int n = 0; n < NDm; n++) hm2 += fd[n] * Tedm[(long)sidx[n] * DD + tid];
        for (int n = 0; n < NPm; n++) hm2 += fp[n] * Tepm[(long)sidx[32 + n] * DD + tid];
    }

    long o = (long)row * DD + tid;
    seq[o]                 = srho[0] * od_ + srho[1] * hd2;
    seq[2097152L + o]      = srho[2] * op_ + srho[3] * hp2;
    seq[2L * 2097152L + o] = srho[4] * om_ + srho[5] * hm2;
}

// ---------------- TF32 tensor-core GEMM (TN), cp.async 2-stage pipeline -------
#define TS2 20

__global__ __launch_bounds__(256, 2) void tgemm_tn(
    const float* __restrict__ A, long Az,
    const float* __restrict__ Bm, long Bz,
    const float* __restrict__ bias, long biasz,
    float* __restrict__ C, long Cz,
    int M, int N, int K)
{
    A += (long)blockIdx.z * Az;
    Bm += (long)blockIdx.z * Bz;
    C += (long)blockIdx.z * Cz;
    const float* bi = bias + (long)blockIdx.z * biasz;

    __shared__ __align__(16) float As[2][128 * TS2];
    __shared__ __align__(16) float Bs[2][128 * TS2];

    int tid = threadIdx.x;
    int warp = tid >> 5, l = tid & 31;
    int wm = warp >> 2, wn = warp & 3;
    int m0 = blockIdx.y * 128, n0 = blockIdx.x * 128;

    int c0r = tid >> 2, c0c = (tid & 3) * 4;
    int c1r = 64 + (tid >> 2), c1c = (tid & 3) * 4;

    const float* Ag = A + (long)m0 * K;
    const float* Bg = Bm + (long)n0 * K;

    float acc[4][4][4];
#pragma unroll
    for (int i = 0; i < 4; i++)
#pragma unroll
        for (int j = 0; j < 4; j++)
#pragma unroll
            for (int c = 0; c < 4; c++) acc[i][j][c] = 0.0f;

    int lq = l >> 2;
    int lk = l & 3;
    int T = K >> 4;

    cpa16(&As[0][c0r * TS2 + c0c], Ag + (long)c0r * K + c0c);
    cpa16(&As[0][c1r * TS2 + c1c], Ag + (long)c1r * K + c1c);
    cpa16(&Bs[0][c0r * TS2 + c0c], Bg + (long)c0r * K + c0c);
    cpa16(&Bs[0][c1r * TS2 + c1c], Bg + (long)c1r * K + c1c);
    cpa_commit();

    for (int t = 0; t < T; t++) {
        int cur = t & 1;
        if (t + 1 < T) {
            int nb = cur ^ 1;
            int ko = (t + 1) * 16;
            cpa16(&As[nb][c0r * TS2 + c0c], Ag + (long)c0r * K + ko + c0c);
            cpa16(&As[nb][c1r * TS2 + c1c], Ag + (long)c1r * K + ko + c1c);
            cpa16(&Bs[nb][c0r * TS2 + c0c], Bg + (long)c0r * K + ko + c0c);
            cpa16(&Bs[nb][c1r * TS2 + c1c], Bg + (long)c1r * K + ko + c1c);
            cpa_commit();
            asm volatile("cp.async.wait_group 1;");
        } else {
            asm volatile("cp.async.wait_group 0;");
        }
        __syncthreads();

#pragma unroll
        for (int kk = 0; kk < 16; kk += 8) {
            uint32_t af[4][4], bf[4][2];
#pragma unroll
            for (int i = 0; i < 4; i++) {
                int ar = wm * 64 + i * 16 + lq;
                af[i][0] = f2tf32(As[cur][ar * TS2 + kk + lk]);
                af[i][1] = f2tf32(As[cur][(ar + 8) * TS2 + kk + lk]);
                af[i][2] = f2tf32(As[cur][ar * TS2 + kk + lk + 4]);
                af[i][3] = f2tf32(As[cur][(ar + 8) * TS2 + kk + lk + 4]);
            }
#pragma unroll
            for (int j = 0; j < 4; j++) {
                int br = wn * 32 + j * 8 + lq;
                bf[j][0] = f2tf32(Bs[cur][br * TS2 + kk + lk]);
                bf[j][1] = f2tf32(Bs[cur][br * TS2 + kk + lk + 4]);
            }
#pragma unroll
            for (int i = 0; i < 4; i++)
#pragma unroll
                for (int j = 0; j < 4; j++) {
                    asm volatile(
                        "mma.sync.aligned.m16n8k8.row.col.f32.tf32.tf32.f32 "
                        "{%0,%1,%2,%3}, {%4,%5,%6,%7}, {%8,%9}, {%0,%1,%2,%3};"
                        : "+f"(acc[i][j][0]), "+f"(acc[i][j][1]),
                          "+f"(acc[i][j][2]), "+f"(acc[i][j][3])
                        : "r"(af[i][0]), "r"(af[i][1]), "r"(af[i][2]), "r"(af[i][3]),
                          "r"(bf[j][0]), "r"(bf[j][1]));
                }
        }
        __syncthreads();
    }

#pragma unroll
    for (int i = 0; i < 4; i++) {
        int r0 = m0 + wm * 64 + i * 16 + lq;
#pragma unroll
        for (int j = 0; j < 4; j++) {
            int cc0 = n0 + wn * 32 + j * 8 + 2 * lk;
            float b0 = bi[cc0], b1 = bi[cc0 + 1];
            *(float2*)&C[(long)r0 * N + cc0] =
                make_float2(acc[i][j][0] + b0, acc[i][j][1] + b1);
            *(float2*)&C[(long)(r0 + 8) * N + cc0] =
                make_float2(acc[i][j][2] + b0, acc[i][j][3] + b1);
        }
    }
}

// ---------------- fused GRU step: gh GEMM (gate-interleaved) + gates ----------
__global__ __launch_bounds__(256, 2) void gru_step(
    const float* __restrict__ hin, const float* __restrict__ whhp,
    const float* __restrict__ bhhp, const float* __restrict__ gi,
    float* __restrict__ hout, int v, float* __restrict__ Hr, int last)
{
    __shared__ __align__(16) float smu[2 * 128 * TS2 * 2];   // 40 KB
    float (*As)[128 * TS2] = (float (*)[128 * TS2])smu;
    float (*Bs)[128 * TS2] = (float (*)[128 * TS2])(smu + 2 * 128 * TS2);
    float* ghs = smu;

    int z = blockIdx.z;
    hin  += (long)z * 262144;
    hout += (long)z * 262144;
    whhp += (long)z * 196608;
    const float* bh = bhhp + (long)z * 768;
    gi   += (long)z * 6291456;

    int tid = threadIdx.x;
    int warp = tid >> 5, l = tid & 31;
    int wm = warp >> 2, wn = warp & 3;
    int n0 = blockIdx.x * 96, m0 = blockIdx.y * 128;
    int d0 = blockIdx.x * 32;

    int c0r = tid >> 2, c0c = (tid & 3) * 4;
    int c1r = 64 + (tid >> 2), c1c = (tid & 3) * 4;

    const float* Ag = hin + (long)m0 * 256;
    const float* Bg = whhp + (long)n0 * 256;
    bool b0ok = c0r < 96;
    bool b1ok = c1r < 96;

    float acc[4][3][4];
#pragma unroll
    for (int i = 0; i < 4; i++)
#pragma unroll
        for (int j = 0; j < 3; j++)
#pragma unroll
            for (int c = 0; c < 4; c++) acc[i][j][c] = 0.0f;

    int lq = l >> 2, lk = l & 3;
    const int T = 16;

    cpa16(&As[0][c0r * TS2 + c0c], Ag + (long)c0r * 256 + c0c);
    cpa16(&As[0][c1r * TS2 + c1c], Ag + (long)c1r * 256 + c1c);
    if (b0ok) cpa16(&Bs[0][c0r * TS2 + c0c], Bg + (long)c0r * 256 + c0c);
    if (b1ok) cpa16(&Bs[0][c1r * TS2 + c1c], Bg + (long)c1r * 256 + c1c);
    cpa_commit();

#pragma unroll 1
    for (int t = 0; t < T; t++) {
        int cur = t & 1;
        if (t + 1 < T) {
            int nb = cur ^ 1;
            int ko = (t + 1) * 16;
            cpa16(&As[nb][c0r * TS2 + c0c], Ag + (long)c0r * 256 + ko + c0c);
            cpa16(&As[nb][c1r * TS2 + c1c], Ag + (long)c1r * 256 + ko + c1c);
            if (b0ok) cpa16(&Bs[nb][c0r * TS2 + c0c], Bg + (long)c0r * 256 + ko + c0c);
            if (b1ok) cpa16(&Bs[nb][c1r * TS2 + c1c], Bg + (long)c1r * 256 + ko + c1c);
            cpa_commit();
            asm volatile("cp.async.wait_group 1;");
        } else {
            asm volatile("cp.async.wait_group 0;");
        }
        __syncthreads();

#pragma unroll
        for (int kk = 0; kk < 16; kk += 8) {
            uint32_t af[4][4], bf[3][2];
#pragma unroll
            for (int i = 0; i < 4; i++) {
                int ar = wm * 64 + i * 16 + lq;
                af[i][0] = f2tf32(As[cur][ar * TS2 + kk + lk]);
                af[i][1] = f2tf32(As[cur][(ar + 8) * TS2 + kk + lk]);
                af[i][2] = f2tf32(As[cur][ar * TS2 + kk + lk + 4]);
                af[i][3] = f2tf32(As[cur][(ar + 8) * TS2 + kk + lk + 4]);
            }
#pragma unroll
            for (int j = 0; j < 3; j++) {
                int br = wn * 24 + j * 8 + lq;
                bf[j][0] = f2tf32(Bs[cur][br * TS2 + kk + lk]);
                bf[j][1] = f2tf32(Bs[cur][br * TS2 + kk + lk + 4]);
            }
#pragma unroll
            for (int i = 0; i < 4; i++)
#pragma unroll
                for (int j = 0; j < 3; j++) {
                    asm volatile(
                        "mma.sync.aligned.m16n8k8.row.col.f32.tf32.tf32.f32 "
                        "{%0,%1,%2,%3}, {%4,%5,%6,%7}, {%8,%9}, {%0,%1,%2,%3};"
                        : "+f"(acc[i][j][0]), "+f"(acc[i][j][1]),
                          "+f"(acc[i][j][2]), "+f"(acc[i][j][3])
                        : "r"(af[i][0]), "r"(af[i][1]), "r"(af[i][2]), "r"(af[i][3]),
                          "r"(bf[j][0]), "r"(bf[j][1]));
                }
        }
        __syncthreads();
    }

#pragma unroll 1
    for (int half = 0; half < 2; half++) {
        if (wm == half) {
#pragma unroll
            for (int i = 0; i < 4; i++) {
                int r0 = i * 16 + lq;
#pragma unroll
                for (int j = 0; j < 3; j++) {
                    int cc0 = wn * 24 + j * 8 + 2 * lk;
                    float b0 = bh[n0 + cc0], b1 = bh[n0 + cc0 + 1];
                    ghs[r0 * 100 + cc0]           = acc[i][j][0] + b0;
                    ghs[r0 * 100 + cc0 + 1]       = acc[i][j][1] + b1;
                    ghs[(r0 + 8) * 100 + cc0]     = acc[i][j][2] + b0;
                    ghs[(r0 + 8) * 100 + cc0 + 1] = acc[i][j][3] + b1;
                }
            }
        }
        __syncthreads();
#pragma unroll
        for (int it = 0; it < 8; it++) {
            int e = tid + it * 256;
            int rr_ = e >> 5, ld = e & 31;
            int b = m0 + half * 64 + rr_;
            int d = d0 + ld;
            const float* gp = gi + ((long)b * VV + v) * 768 + 3 * d;
            float ghr = ghs[rr_ * 100 + 3 * ld];
            float ghz = ghs[rr_ * 100 + 3 * ld + 1];
            float ghn = ghs[rr_ * 100 + 3 * ld + 2];
            float r  = sigm(gp[0] + ghr);
            float zz = sigm(gp[1] + ghz);
            float nn = tanhf(gp[2] + r * ghn);
            float hold = hin[(long)b * 256 + d];
            float hnew = (1.0f - zz) * nn + zz * hold;
            hout[(long)b * 256 + d] = hnew;
            if (last) Hr[(long)b * 768 + z * 256 + d] = fmaxf(hnew, 0.0f);
        }
        __syncthreads();
    }
}

// ---------------- GRU gate 0 (h=0 -> gh = bhh), permuted layout ----------------
__global__ void gate0_kernel(const float* __restrict__ gi, const float* __restrict__ bhhp,
                             float* __restrict__ h)
{
    int idx = blockIdx.x * 256 + threadIdx.x;
    int z = idx >> 18;
    int rem = idx & 262143;
    int b = rem >> 8;
    int d = rem & 255;
    const float* girow = gi + ((long)z * 8192 + (long)b * VV) * 768 + 3 * d;
    const float* bh = bhhp + (long)z * 768 + 3 * d;
    float rr = sigm(girow[0] + bh[0]);
    float zz = sigm(girow[1] + bh[1]);
    float nn = tanhf(girow[2] + rr * bh[2]);
    h[idx] = (1.0f - zz) * nn;
}

__global__ void final1_kernel(const float* __restrict__ scorepad,
                              const float* __restrict__ ddi,
                              float* __restrict__ out, float* __restrict__ partials)
{
    __shared__ float p[VOC_M];
    __shared__ float red[256];
    int b = blockIdx.x, tid = threadIdx.x;
    if (tid < VOC_M) {
        float s = scorepad[(long)b * 256 + tid];
        out[(long)b * VOC_M + tid] = s;
        p[tid] = sigm(s);
    }
    __syncthreads();
    float part = 0.0f;
    if (tid < VOC_M) {
        float inner = 0.0f;
        for (int i = 0; i < VOC_M; i++) inner += p[i] * ddi[(long)i * VOC_M + tid];
        part = p[tid] * inner;
    }
    red[tid] = part;
    __syncthreads();
    for (int s = 128; s > 0; s >>= 1) {
        if (tid < s) red[tid] += red[tid + s];
        __syncthreads();
    }
    if (tid == 0) partials[b] = red[0];
}

__global__ void final2_kernel(const float* __restrict__ partials,
                              float* __restrict__ out, int out_size)
{
    __shared__ float red[256];
    int tid = threadIdx.x;
    float s = partials[tid] + partials[tid + 256] + partials[tid + 512] + partials[tid + 768];
    red[tid] = s;
    __syncthreads();
    for (int st = 128; st > 0; st >>= 1) {
        if (tid < st) red[tid] += red[tid + st];
        __syncthreads();
    }
    if (tid == 0 && out_size > BB * VOC_M) out[BB * VOC_M] = 0.0005f * red[0];
}

// ---------------- host launch ----------------
extern "C" void kernel_launch(void* const* d_in, const int* in_sizes, int n_in,
                              void* d_out, int out_size)
{
    const int* idx_diag = (const int*)d_in[0];
    const int* idx_proc = (const int*)d_in[1];
    const int* idx_med  = (const int*)d_in[2];
    const float* adj_diag = (const float*)d_in[3];
    const float* adj_proc = (const float*)d_in[4];
    const float* adj_med  = (const float*)d_in[5];
    const float* w_dm = (const float*)d_in[6];
    const float* w_pm = (const float*)d_in[7];
    const float* E_diag = (const float*)d_in[8];
    const float* E_proc = (const float*)d_in[9];
    const float* E_med  = (const float*)d_in[10];
    const float* W_homo = (const float*)d_in[11];
    const float* Wh_d  = (const float*)d_in[12];
    const float* Wh_p  = (const float*)d_in[13];
    const float* Wh_md = (const float*)d_in[14];
    const float* Wh_mp = (const float*)d_in[15];
    const float* rho   = (const float*)d_in[16];
    const float* gru_wih = (const float*)d_in[17];
    const float* gru_whh = (const float*)d_in[18];
    const float* gru_bih = (const float*)d_in[19];
    const float* gru_bhh = (const float*)d_in[20];
    const float* Wq = (const float*)d_in[21];
    const float* bq = (const float*)d_in[22];
    const float* ddi = (const float*)d_in[23];

    void* sp = nullptr;
    cudaGetSymbolAddress(&sp, g_scratch);
    float* S = (float*)sp;

    float* HEd   = S + OFF_HED;
    float* HEp   = S + OFF_HEP;
    float* HEm   = S + OFF_HEM;
    float* Temd  = S + OFF_TEMD;
    float* Temp_ = S + OFF_TEMP;
    float* Tedm  = S + OFF_TEDM;
    float* Tepm  = S + OFF_TEPM;
    float* seq   = S + OFF_SEQ;
    float* gi    = S + OFF_GI;
    float* h0    = S + OFF_H0;
    float* h1    = S + OFF_H1;
    float* Hr    = S + OFF_HR;
    float* Wq2p  = S + OFF_WQ2;
    float* bqp   = S + OFF_BQP;
    float* spad  = S + OFF_SP;
    float* part  = S + OFF_PART;
    float* WIHP  = S + OFF_WIHP;
    float* WHHP  = S + OFF_WHHP;
    float* BIHP  = S + OFF_BIHP;
    float* BHHP  = S + OFF_BHHP;

    static int smem_set = 0;
    if (!smem_set) {
        cudaFuncSetAttribute(graph_kernel,
                             cudaFuncAttributeMaxDynamicSharedMemorySize, GRAPH_SMEM);
        smem_set = 1;
    }

    // 1) tables + wq2 + weight permutes
    tables_kernel<<<1010, 256>>>(E_diag, E_proc, E_med, W_homo, Wh_d, Wh_p, Wh_md, Wh_mp,
                                 Wq, bq, gru_wih, gru_whh, gru_bih, gru_bhh,
                                 HEd, HEp, HEm, Temd, Temp_, Tedm, Tepm, Wq2p, bqp,
                                 WIHP, WHHP, BIHP, BHHP);

    // 2) fused per-visit graph kernel (all phases concurrent, 100KB dyn smem)
    graph_kernel<<<BB * VV, 256, GRAPH_SMEM>>>(idx_diag, idx_proc, idx_med,
                                               adj_diag, adj_proc, adj_med, w_dm, w_pm, rho,
                                               HEd, HEp, HEm, Temd, Temp_, Tedm, Tepm, seq);

    // 3) gi = seq @ wihp^T + bihp
    tgemm_tn<<<dim3(6, 64, 3), 256>>>(seq, 8192L * 256, WIHP, 768L * 256,
                                      BIHP, 768, gi, 8192L * 768,
                                      8192, 768, 256);

    // 4) GRU recurrence
    gate0_kernel<<<3072, 256>>>(gi, BHHP, h0);
    float* hb[2] = {h0, h1};
    for (int v = 1; v < VV; v++) {
        gru_step<<<dim3(8, 8, 3), 256>>>(hb[(v - 1) & 1], WHHP, BHHP, gi,
                                         hb[v & 1], v, Hr, v == VV - 1);
    }

    // 5) final score GEMM
    tgemm_tn<<<dim3(2, 8, 1), 256>>>(Hr, 0, Wq2p, 0, bqp, 0, spad, 0,
                                     1024, 256, 768);

    // 6) outputs
    final1_kernel<<<BB, 256>>>(spad, ddi, (float*)d_out, part);
    final2_kernel<<<1, 256>>>(part, (float*)d_out, out_size);
}